// round 16
// baseline (speedup 1.0000x reference)
#include <cuda_runtime.h>
#include <cuda_fp16.h>
#include <cstdint>

// out[n,R,C,co] = active[n,R/14,C/14] * (bias[co] + sum_{dy,dx,ci} x[n,R+dy,C+dx,ci]*k[dy,dx,ci,co])
// valid 3x3 conv 506x506 -> 504x504, gated per 14x14 tile by mask-block max > 0.5
//
// fp16 single-product mma.sync, NO prep pass:
//   persistent 296 CTAs, 2 CTAs/SM, 256 thr, tile 16x24, warp = 3 cols x 16 rows.
//   Pipeline stage = (tile, ci-half16): cp.async fp32 half-tile -> in-place
//   convert to fp16 (same 80B slot) -> MMA. Double-buffered stages; accumulators
//   carry across the two halves of a tile.

#define N_IMG 8
#define H_IN  506
#define W_IN  506
#define H_OUT 504
#define W_OUT 504
#define NBH   36
#define NBW   36

#define RT_CNT 32                     // 16-row tiles (rows 496.. guarded)
#define CT_CNT 21                     // 24-col tiles: 21*24 = 504 exact
#define TPI    (RT_CNT * CT_CNT)      // 672
#define N_TILES (N_IMG * TPI)         // 5376
#define GRID_CONV 296

#define THREADS 256

#define XROWP 26                      // pixel columns per row (24 + 2 halo)
#define PIXB  80                      // slot: fp32 half 64B staged, fp16 32B after
#define NPIX  (18 * XROWP)            // 468
#define XBUF  (NPIX * PIXB)           // 37440 per buffer
#define WROWB 80                      // 64B fp16 ci (both halves) + 16 pad
#define WS_BYTES (9 * 32 * WROWB)     // 23040
#define SMEM_BYTES (2 * XBUF + WS_BYTES)   // 97920 -> 2 CTAs/SM

__device__ float g_active[N_IMG * NBH * NBW];

// ------------------------- helpers ------------------------------------------
__device__ __forceinline__ uint32_t smem_u32(const void* p) {
    uint32_t a;
    asm("{ .reg .u64 t; cvta.to.shared.u64 t, %1; cvt.u32.u64 %0, t; }"
        : "=r"(a) : "l"(p));
    return a;
}
__device__ __forceinline__ void sts64(uint32_t a, uint64_t v) {
    asm volatile("st.shared.b64 [%0], %1;" :: "r"(a), "l"(v) : "memory");
}
__device__ __forceinline__ void cp_async16(uint32_t dst, const void* src) {
    asm volatile("cp.async.cg.shared.global [%0], [%1], 16;"
                 :: "r"(dst), "l"(src) : "memory");
}
__device__ __forceinline__ void cp_commit() {
    asm volatile("cp.async.commit_group;" ::: "memory");
}
__device__ __forceinline__ void cp_wait0() {
    asm volatile("cp.async.wait_group 0;" ::: "memory");
}
__device__ __forceinline__ void ldsm4(uint32_t* r, uint32_t addr) {
    asm volatile("ldmatrix.sync.aligned.m8n8.x4.shared.b16 {%0,%1,%2,%3}, [%4];"
                 : "=r"(r[0]), "=r"(r[1]), "=r"(r[2]), "=r"(r[3]) : "r"(addr));
}
__device__ __forceinline__ void mma4(float* d, const uint32_t* a, const uint32_t* b) {
    asm volatile(
        "mma.sync.aligned.m16n8k16.row.col.f32.f16.f16.f32 "
        "{%0,%1,%2,%3},{%4,%5,%6,%7},{%8,%9},{%0,%1,%2,%3};"
        : "+f"(d[0]), "+f"(d[1]), "+f"(d[2]), "+f"(d[3])
        : "r"(a[0]), "r"(a[1]), "r"(a[2]), "r"(a[3]), "r"(b[0]), "r"(b[1]));
}

// ---------------- kernel 1: mask block max -> active flag -------------------
__global__ void __launch_bounds__(256) mask_kernel(const float* __restrict__ mask) {
    __shared__ float red[256];
    int b = blockIdx.x;
    int n   = b / (NBH * NBW);
    int rem = b % (NBH * NBW);
    int bi = rem / NBW, bj = rem % NBW;
    int tid = threadIdx.x;
    int rr = tid >> 4, cc = tid & 15;
    red[tid] = mask[(n * H_IN + bi * 14 + rr) * W_IN + bj * 14 + cc];
    __syncthreads();
    #pragma unroll
    for (int s = 128; s > 0; s >>= 1) {
        if (tid < s) red[tid] = fmaxf(red[tid], red[tid + s]);
        __syncthreads();
    }
    if (tid == 0) g_active[b] = (red[0] > 0.5f) ? 1.0f : 0.0f;
}

// ---------------- cp.async prefetch of one (tile, ci-half) stage -------------
__device__ __forceinline__ void issue_stage(
    const float* __restrict__ x, uint32_t dstbase, int n, int R0, int C0, int h,
    int tid)
{
    for (int p = tid; p < NPIX; p += THREADS) {
        int ir = p / XROWP, ic = p - ir * XROWP;
        int gr = R0 + ir; if (gr > H_IN - 1) gr = H_IN - 1;
        int gc = C0 + ic;                 // <= 480+25 = 505, in range
        const float* src = x + (((size_t)n * H_IN + gr) * W_IN + gc) * 32 + h * 16;
        uint32_t dst = dstbase + (uint32_t)(p * PIXB);
        #pragma unroll
        for (int c = 0; c < 4; c++)
            cp_async16(dst + c * 16, src + c * 4);
    }
}

// ---------------- kernel 2: persistent conv, fused-convert pipeline ----------
__global__ void __launch_bounds__(THREADS, 2) conv_mma_kernel(
    const float* __restrict__ x,
    const float* __restrict__ kern,
    const float* __restrict__ bias,
    float* __restrict__ out)
{
    extern __shared__ char smem[];
    const uint32_t xs0 = smem_u32(smem);
    const uint32_t ws  = xs0 + 2 * XBUF;
    const int tid = threadIdx.x;
    const int wid = tid >> 5;
    const int lid = tid & 31;
    const int bid = blockIdx.x;

    // ---- stage weights once: kern[tap][ci][co] -> ws[tap][co][ci fp16] ----
    for (int j = tid; j < 2304; j += THREADS) {
        int ciq = j & 7;
        int co  = (j >> 3) & 31;
        int tap = j >> 8;
        int ci  = ciq * 4;
        const float* kp = kern + (tap * 32 + ci) * 32 + co;
        __half2 p0 = __floats2half2_rn(kp[0],  kp[32]);
        __half2 p1 = __floats2half2_rn(kp[64], kp[96]);
        uint64_t v = (uint64_t)(*reinterpret_cast<uint32_t*>(&p0))
                   | ((uint64_t)(*reinterpret_cast<uint32_t*>(&p1)) << 32);
        sts64(ws + (uint32_t)((tap * 32 + co) * WROWB + ciq * 8), v);
    }

    // per-lane ldmatrix base addresses; warp = 3 output cols (cw..cw+2)
    const int cw = wid * 3;
    const int irl = (lid & 7) + 8 * ((lid >> 3) & 1);
    const uint32_t baseAoff = (uint32_t)
        ((irl * XROWP + cw) * PIXB + ((lid >> 4) & 1) * 16);
    const uint32_t baseB = ws + (uint32_t)
        ((((lid & 7) + ((lid >> 4) << 3)) * WROWB) + ((lid >> 3) & 1) * 16);

    const int n2 = (lid & 3) * 2;
    float2 bv[4];
    #pragma unroll
    for (int nb = 0; nb < 4; nb++)
        bv[nb] = *(const float2*)(bias + nb * 8 + n2);

    const int nT = (N_TILES - bid + GRID_CONV - 1) / GRID_CONV;
    const int nS = nT * 2;                 // stages = (tile, ci-half)

    // prologue: prefetch stage 0 (tile 0, half 0) into buffer 0
    {
        int t = bid;
        int n = t / TPI, rem = t % TPI;
        issue_stage(x, xs0, n, (rem / CT_CNT) * 16, (rem % CT_CNT) * 24, 0, tid);
        cp_commit();
    }

    float d[3][4][4];

    for (int s = 0; s < nS; s++) {
        const int k = s >> 1;
        const int h = s & 1;
        const int t   = bid + k * GRID_CONV;
        const int n   = t / TPI;
        const int rem = t % TPI;
        const int R0 = (rem / CT_CNT) * 16;
        const int C0 = (rem % CT_CNT) * 24;
        const uint32_t buf = xs0 + (uint32_t)((s & 1) * 0 + ((s & 1) ? XBUF : 0));
        // (buffer select = s parity)
        const uint32_t bufb = xs0 + (uint32_t)((s & 1) * XBUF);

        cp_wait0();                       // this thread's fp32 pixels arrived

        // ---- in-place convert: own pixels fp32[0,64) -> fp16[0,32) ----
        for (int p = tid; p < NPIX; p += THREADS) {
            const char* sp = smem + ((s & 1) * XBUF) + p * PIXB;
            float4 a = *(const float4*)(sp);
            float4 b = *(const float4*)(sp + 16);
            float4 c = *(const float4*)(sp + 32);
            float4 e = *(const float4*)(sp + 48);
            __half2 h0 = __floats2half2_rn(a.x, a.y);
            __half2 h1 = __floats2half2_rn(a.z, a.w);
            __half2 h2 = __floats2half2_rn(b.x, b.y);
            __half2 h3 = __floats2half2_rn(b.z, b.w);
            __half2 h4 = __floats2half2_rn(c.x, c.y);
            __half2 h5 = __floats2half2_rn(c.z, c.w);
            __half2 h6 = __floats2half2_rn(e.x, e.y);
            __half2 h7 = __floats2half2_rn(e.z, e.w);
            uint4 v0, v1;
            v0.x = *reinterpret_cast<uint32_t*>(&h0);
            v0.y = *reinterpret_cast<uint32_t*>(&h1);
            v0.z = *reinterpret_cast<uint32_t*>(&h2);
            v0.w = *reinterpret_cast<uint32_t*>(&h3);
            v1.x = *reinterpret_cast<uint32_t*>(&h4);
            v1.y = *reinterpret_cast<uint32_t*>(&h5);
            v1.z = *reinterpret_cast<uint32_t*>(&h6);
            v1.w = *reinterpret_cast<uint32_t*>(&h7);
            char* dp = (char*)smem + ((s & 1) * XBUF) + p * PIXB;
            *(uint4*)(dp)      = v0;
            *(uint4*)(dp + 16) = v1;
        }
        __syncthreads();                  // fp16 visible to all; prev buf free

        // prefetch next stage into the other buffer (fully async)
        if (s + 1 < nS) {
            int s1 = s + 1;
            int t1 = bid + (s1 >> 1) * GRID_CONV;
            int n1 = t1 / TPI, rem1 = t1 % TPI;
            issue_stage(x, xs0 + (uint32_t)((s1 & 1) * XBUF), n1,
                        (rem1 / CT_CNT) * 16, (rem1 % CT_CNT) * 24, s1 & 1, tid);
            cp_commit();
        }

        if (h == 0) {
            #pragma unroll
            for (int f = 0; f < 3; f++)
                #pragma unroll
                for (int nb = 0; nb < 4; nb++)
                    #pragma unroll
                    for (int e = 0; e < 4; e++) d[f][nb][e] = 0.0f;
        }

        // ---- MMA over this ci-half: dy x dx, 5 A-frags shared across dx ----
        const uint32_t baseA = bufb + baseAoff;
        #pragma unroll 1
        for (int dy = 0; dy < 3; dy++) {
            uint32_t A[20], B[8];
            const uint32_t ao = baseA + (uint32_t)(dy * XROWP * PIXB);
            #pragma unroll
            for (int j = 0; j < 5; j++)
                ldsm4(A + 4 * j, ao + j * PIXB);
            #pragma unroll
            for (int dx = 0; dx < 3; dx++) {
                const uint32_t bo = baseB
                    + (uint32_t)((dy * 3 + dx) * (32 * WROWB) + h * 32);
                ldsm4(B,     bo);
                ldsm4(B + 4, bo + 16 * WROWB);
                #pragma unroll
                for (int f = 0; f < 3; f++)
                    #pragma unroll
                    for (int nb = 0; nb < 4; nb++)
                        mma4(d[f][nb], A + 4 * (f + dx), B + 2 * nb);
            }
        }

        // ---- epilogue after second half ----
        if (h == 1) {
            const int r0 = lid >> 2;
            const int R1 = R0 + r0;
            const int R2 = R1 + 8;
            const bool r2ok = (R2 < H_OUT);
            const int R2c = r2ok ? R2 : H_OUT - 1;
            const float* act1 = g_active + (n * NBH + R1 / 14) * NBW;
            const float* act2 = g_active + (n * NBH + R2c / 14) * NBW;

            #pragma unroll
            for (int f = 0; f < 3; f++) {
                const int C = C0 + cw + f;
                const int cb = C / 14;
                float fg1 = act1[cb];
                float* o1 = out + (((size_t)n * H_OUT + R1) * W_OUT + C) * 32 + n2;
                #pragma unroll
                for (int nb = 0; nb < 4; nb++) {
                    float2 v;
                    v.x = (d[f][nb][0] + bv[nb].x) * fg1;
                    v.y = (d[f][nb][1] + bv[nb].y) * fg1;
                    *(float2*)(o1 + nb * 8) = v;
                }
                if (r2ok) {
                    float fg2 = act2[cb];
                    float* o2 = out + (((size_t)n * H_OUT + R2) * W_OUT + C) * 32 + n2;
                    #pragma unroll
                    for (int nb = 0; nb < 4; nb++) {
                        float2 v;
                        v.x = (d[f][nb][2] + bv[nb].x) * fg2;
                        v.y = (d[f][nb][3] + bv[nb].y) * fg2;
                        *(float2*)(o2 + nb * 8) = v;
                    }
                }
            }
        }
        (void)buf;
    }
}

// ---------------------------------------------------------------------------
extern "C" void kernel_launch(void* const* d_in, const int* in_sizes, int n_in,
                              void* d_out, int out_size)
{
    const float* x    = (const float*)d_in[0];
    const float* mask = (const float*)d_in[1];
    const float* kern = (const float*)d_in[2];
    const float* bias = (const float*)d_in[3];
    float* out = (float*)d_out;
    (void)in_sizes; (void)n_in; (void)out_size;

    cudaFuncSetAttribute(conv_mma_kernel,
                         cudaFuncAttributeMaxDynamicSharedMemorySize, SMEM_BYTES);

    mask_kernel<<<N_IMG * NBH * NBW, 256>>>(mask);
    conv_mma_kernel<<<GRID_CONV, THREADS, SMEM_BYTES>>>(x, kern, bias, out);
}